// round 13
// baseline (speedup 1.0000x reference)
#include <cuda_runtime.h>
#include <cuda_fp16.h>
#include <cstdint>

// Problem constants
#define NN 32
#define HH 56
#define WW 56
#define CC 256
#define PP (NN * HH * WW)   // 100352 pixels
#define SEGS 784            // 128-pixel segments

// ---------------------------------------------------------------------------
// Scratch: transposed fp16 weights B[n][k] only (A never leaves the CTA).
// ---------------------------------------------------------------------------
__device__ __align__(256) __half g_b[CC * CC];

// ---------------------------------------------------------------------------
// PTX helpers
// ---------------------------------------------------------------------------
__device__ __forceinline__ uint32_t smem_u32(const void* p) {
    uint32_t a;
    asm("{ .reg .u64 t; cvta.to.shared.u64 t, %1; cvt.u32.u64 %0, t; }"
        : "=r"(a) : "l"(p));
    return a;
}
#define CP16(sa, gp) \
    asm volatile("cp.async.cg.shared.global [%0], [%1], 16;" \
                 :: "r"((uint32_t)(sa)), "l"(gp) : "memory")
#define CP_COMMIT() asm volatile("cp.async.commit_group;" ::: "memory")
#define CP_WAIT2()  asm volatile("cp.async.wait_group 2;" ::: "memory")

__device__ __forceinline__ void ldsm4(uint32_t r[4], uint32_t a) {
    asm volatile("ldmatrix.sync.aligned.m8n8.x4.shared.b16 {%0,%1,%2,%3}, [%4];"
                 : "=r"(r[0]), "=r"(r[1]), "=r"(r[2]), "=r"(r[3]) : "r"(a));
}
__device__ __forceinline__ void mma16816(float c[4],
                                         const uint32_t a[4],
                                         uint32_t b0, uint32_t b1) {
    asm volatile(
        "mma.sync.aligned.m16n8k16.row.col.f32.f16.f16.f32 "
        "{%0,%1,%2,%3}, {%4,%5,%6,%7}, {%8,%9}, {%0,%1,%2,%3};"
        : "+f"(c[0]), "+f"(c[1]), "+f"(c[2]), "+f"(c[3])
        : "r"(a[0]), "r"(a[1]), "r"(a[2]), "r"(a[3]), "r"(b0), "r"(b1));
}

// pack float4 -> 2x half2 (8 bytes)
__device__ __forceinline__ uint2 pack_h4(float4 v) {
    __half2 a = __floats2half2_rn(v.x, v.y);
    __half2 b = __floats2half2_rn(v.z, v.w);
    uint2 u;
    u.x = *(uint32_t*)&a;
    u.y = *(uint32_t*)&b;
    return u;
}

// ---------------------------------------------------------------------------
// Kernel 0 (prep): transpose pw_kernel -> g_b [n][k] fp16.
// ---------------------------------------------------------------------------
__global__ void __launch_bounds__(256) prep_kernel(const float* __restrict__ pwk) {
    const int idx = blockIdx.x * 256 + threadIdx.x;  // 65536 total
    const int k = idx >> 8, n = idx & 255;
    g_b[(size_t)n * CC + k] = __float2half_rn(pwk[(size_t)k * CC + n]);
}

// ---------------------------------------------------------------------------
// Fully fused kernel: per CTA (128 px x 128 cols):
//   phase 1: issue B cp.async prologue (L2-hot), then compute dw(128 px) in
//            fp32 regs -> fp16 smem A tile [128][256] (resident, stride 528B).
//   phase 2: K-loop: A from resident smem (ldmatrix), B streamed 4-stage.
// dw is computed twice (once per bn CTA); the bn pair is dispatched adjacently
// so x reads L2-hit on the second pass. No inter-CTA sync at all.
// ---------------------------------------------------------------------------
#define STRIDEA 528                    // 256*2 + 16 pad; banks 4r mod 32 distinct
#define OFF_A 0
#define A_BYTES (128 * STRIDEA)        // 67584
#define STRIDEB 80
#define B_TILE (128 * STRIDEB)         // 10240 per [128][32] stage
#define OFF_BST A_BYTES                // 4 stages
#define OFF_INV (OFF_BST + 4 * B_TILE) // 108544
#define OFF_B2  (OFF_INV + 512)
#define SMEM_BYTES (OFF_B2 + 512)      // 109568 -> 2 CTAs/SM

__global__ void __launch_bounds__(256, 2) fused_kernel(
    const float* __restrict__ x,
    const float* __restrict__ dwk,
    const float* __restrict__ dwb,
    const float* __restrict__ pwb,
    const float* __restrict__ gma,
    const float* __restrict__ bta,
    const float* __restrict__ mmean,
    const float* __restrict__ mvar,
    float* __restrict__ out)
{
    extern __shared__ __align__(128) char smem[];
    const uint32_t sb = smem_u32(smem);
    const int t = threadIdx.x;
    const int lane = t & 31, wid = t >> 5;
    const int bn = blockIdx.x * 128;
    const int seg = blockIdx.y;
    const int bm = seg * 128;

    // BN constants
    float* sinv = (float*)(smem + OFF_INV);
    float* sbb  = (float*)(smem + OFF_B2);
    if (t < 128) {
        const int nn = bn + t;
        const float iv = gma[nn] * rsqrtf(mvar[nn] + 1e-3f);
        sinv[t] = iv;
        sbb[t]  = fmaf(pwb[nn], iv, bta[nn] - mmean[nn] * iv);
    }

    // B loader: thread t -> row t>>1, 32B half t&1 (2 cp16 per stage)
    const __half* gB = g_b + (size_t)(bn + (t >> 1)) * CC + (t & 1) * 16;
    const uint32_t sdB = sb + OFF_BST + (t >> 1) * STRIDEB + (t & 1) * 32;

#define ISSUE(k0, stoff) do {                                               \
    CP16(sdB + (stoff) + 0,   gB + (k0));                                   \
    CP16(sdB + (stoff) + 16,  gB + (k0) + 8);                               \
    CP_COMMIT();                                                            \
} while (0)

    // B prologue overlaps the dw phase below
    ISSUE(0, 0);
    ISSUE(32, B_TILE);
    ISSUE(64, 2 * B_TILE);

    // ------------------- phase 1: dw -> resident smem A -------------------
    {
        const int c = (t & 63) * 4;     // channel group (4 ch)
#pragma unroll
        for (int iter = 0; iter < 4; iter++) {
            const int octl = (t >> 6) + iter * 4;      // 0..15 local oct
            const int oct  = seg * 16 + octl;
            const int w0 = (oct % 7) * 8;
            const int nh = oct / 7;
            const int h = nh % HH;
            const int n = nh / HH;

            const float4 bias = *(const float4*)(dwb + c);
            float4 acc[8];
#pragma unroll
            for (int px = 0; px < 8; px++) acc[px] = bias;

#pragma unroll
            for (int kh = 0; kh < 3; kh++) {
                const int hh = h + 2 * kh - 2;
                if ((unsigned)hh >= (unsigned)HH) continue;
                const float* xrow = x + ((size_t)(n * HH + hh) * WW) * CC + c;

                const float4 k0 = *(const float4*)(dwk + (kh * 3 + 0) * CC + c);
                const float4 k1 = *(const float4*)(dwk + (kh * 3 + 1) * CC + c);
                const float4 k2 = *(const float4*)(dwk + (kh * 3 + 2) * CC + c);

                float4 col[12];
#pragma unroll
                for (int j = 0; j < 12; j++) {
                    const int ww = w0 - 2 + j;
                    if ((unsigned)ww < (unsigned)WW) {
                        float4 v = *(const float4*)(xrow + (size_t)ww * CC);
                        v.x = fmaxf(v.x, 0.0f); v.y = fmaxf(v.y, 0.0f);
                        v.z = fmaxf(v.z, 0.0f); v.w = fmaxf(v.w, 0.0f);
                        col[j] = v;
                    } else {
                        col[j] = make_float4(0.f, 0.f, 0.f, 0.f);
                    }
                }
#pragma unroll
                for (int px = 0; px < 8; px++) {
                    acc[px].x = fmaf(col[px].x, k0.x, fmaf(col[px + 2].x, k1.x, fmaf(col[px + 4].x, k2.x, acc[px].x)));
                    acc[px].y = fmaf(col[px].y, k0.y, fmaf(col[px + 2].y, k1.y, fmaf(col[px + 4].y, k2.y, acc[px].y)));
                    acc[px].z = fmaf(col[px].z, k0.z, fmaf(col[px + 2].z, k1.z, fmaf(col[px + 4].z, k2.z, acc[px].z)));
                    acc[px].w = fmaf(col[px].w, k0.w, fmaf(col[px + 2].w, k1.w, fmaf(col[px + 4].w, k2.w, acc[px].w)));
                }
            }

            // store 8 px x 4 ch as fp16 into resident A tile
            const uint32_t abase = sb + OFF_A + (octl * 8) * STRIDEA + c * 2;
#pragma unroll
            for (int px = 0; px < 8; px++) {
                uint2 u = pack_h4(acc[px]);
                asm volatile("st.shared.v2.b32 [%0], {%1, %2};"
                             :: "r"(abase + px * STRIDEA), "r"(u.x), "r"(u.y));
            }
        }
    }
    __syncthreads();   // A tile complete

    // --------------------------- phase 2: GEMM ---------------------------
    const int wm = wid & 1, wn = wid >> 1;   // 2m x 4n, warp tile 64x32
    const int r = lane >> 2, tg = lane & 3;

    float acc[4][4][4];
#pragma unroll
    for (int mt = 0; mt < 4; mt++)
#pragma unroll
        for (int nt = 0; nt < 4; nt++)
#pragma unroll
            for (int i = 0; i < 4; i++) acc[mt][nt][i] = 0.0f;

    // ldmatrix lane addresses
    const uint32_t aAddr = sb + OFF_A + (wm * 64 + (lane & 15)) * STRIDEA + (lane >> 4) * 16;
    const uint32_t bAddr = sb + OFF_BST +
        (wn * 32 + ((lane >> 4) << 3) + (lane & 7)) * STRIDEB + ((lane >> 3) & 1) * 16;

    uint32_t st = 0;                 // compute-stage byte offset (B ring)
    uint32_t ist = 3 * B_TILE;       // issue-stage byte offset

    for (int c = 0; c < 8; c++) {
        CP_WAIT2();                  // B stage c complete
        __syncthreads();             // protects B buffer reuse
        if (c < 5) {
            ISSUE((c + 3) * 32, ist);
            ist = (ist == 3 * B_TILE) ? 0u : ist + B_TILE;
        } else {
            CP_COMMIT();             // keep group counting aligned
        }

        // B fragments for both k16 halves of this chunk
        uint32_t bf[2][2][4];
#pragma unroll
        for (int k16 = 0; k16 < 2; k16++)
#pragma unroll
            for (int np = 0; np < 2; np++)
                ldsm4(bf[k16][np], bAddr + st + np * (16 * STRIDEB) + k16 * 32);

        // A fragments from resident tile, pipelined one step ahead
        const uint32_t aBase = aAddr + c * 64;   // chunk k-offset (32 halfs)
        uint32_t acur[4], anxt[4];
        ldsm4(acur, aBase);          // (k16=0, mt=0)
#pragma unroll
        for (int s = 0; s < 8; s++) {
            const int k16 = s >> 2, mt = s & 3;
            if (s < 7) {
                const int s2 = s + 1;
                ldsm4(anxt, aBase + (s2 & 3) * (16 * STRIDEA) + (s2 >> 2) * 32);
            }
#pragma unroll
            for (int np = 0; np < 2; np++) {
#pragma unroll
                for (int half = 0; half < 2; half++) {
                    mma16816(acc[mt][np * 2 + half], acur,
                             bf[k16][np][half * 2], bf[k16][np][half * 2 + 1]);
                }
            }
#pragma unroll
            for (int i = 0; i < 4; i++) acur[i] = anxt[i];
        }
        st = (st == 3 * B_TILE) ? 0u : st + B_TILE;
    }

    // Epilogue: BN scale/offset + store
#pragma unroll
    for (int mt = 0; mt < 4; mt++) {
        const int row0 = bm + wm * 64 + mt * 16 + r;
#pragma unroll
        for (int nt = 0; nt < 4; nt++) {
            const int cl = wn * 32 + nt * 8 + tg * 2;   // local col 0..127
            const float i0 = sinv[cl], i1 = sinv[cl + 1];
            const float o0 = sbb[cl],  o1 = sbb[cl + 1];
            float2 v0, v1;
            v0.x = fmaf(acc[mt][nt][0], i0, o0);
            v0.y = fmaf(acc[mt][nt][1], i1, o1);
            v1.x = fmaf(acc[mt][nt][2], i0, o0);
            v1.y = fmaf(acc[mt][nt][3], i1, o1);
            *(float2*)(out + (size_t)row0 * CC + bn + cl)       = v0;
            *(float2*)(out + (size_t)(row0 + 8) * CC + bn + cl) = v1;
        }
    }
#undef ISSUE
}

// ---------------------------------------------------------------------------
// Launch
// ---------------------------------------------------------------------------
extern "C" void kernel_launch(void* const* d_in, const int* in_sizes, int n_in,
                              void* d_out, int out_size)
{
    const float* x     = (const float*)d_in[0];
    const float* dwk   = (const float*)d_in[1];
    const float* dwb   = (const float*)d_in[2];
    const float* pwk   = (const float*)d_in[3];
    const float* pwb   = (const float*)d_in[4];
    const float* gma   = (const float*)d_in[5];
    const float* bta   = (const float*)d_in[6];
    const float* mmean = (const float*)d_in[7];
    const float* mvar  = (const float*)d_in[8];
    float* out = (float*)d_out;

    static int smem_set = 0;
    if (!smem_set) {
        cudaFuncSetAttribute(fused_kernel,
                             cudaFuncAttributeMaxDynamicSharedMemorySize, SMEM_BYTES);
        smem_set = 1;
    }

    prep_kernel<<<256, 256>>>(pwk);
    fused_kernel<<<dim3(2, SEGS), 256, SMEM_BYTES>>>(
        x, dwk, dwb, pwb, gma, bta, mmean, mvar, out);
}

// round 14
// speedup vs baseline: 1.0116x; 1.0116x over previous
#include <cuda_runtime.h>
#include <cuda_fp16.h>
#include <cstdint>

// Problem constants
#define NN 32
#define HH 56
#define WW 56
#define CC 256
#define PP (NN * HH * WW)   // 100352 pixels

#define SEGS 784            // 128-pixel segments
#define LAG 56              // gemm trails dw by LAG groups (672 blocks > 444 window)
#define GROUPS (SEGS + LAG) // 840
#define TOTAL_BLOCKS (GROUPS * 12)  // 10080

// ---------------------------------------------------------------------------
// Scratch: dw output fp16, transposed fp16 weights, per-segment ready counters.
// ---------------------------------------------------------------------------
__device__ __align__(256) __half g_a[(size_t)PP * CC];
__device__ __align__(256) __half g_b[CC * CC];
__device__ int g_cnt[SEGS];

// ---------------------------------------------------------------------------
// PTX helpers
// ---------------------------------------------------------------------------
__device__ __forceinline__ uint32_t smem_u32(const void* p) {
    uint32_t a;
    asm("{ .reg .u64 t; cvta.to.shared.u64 t, %1; cvt.u32.u64 %0, t; }"
        : "=r"(a) : "l"(p));
    return a;
}
#define CP16(sa, gp) \
    asm volatile("cp.async.cg.shared.global [%0], [%1], 16;" \
                 :: "r"((uint32_t)(sa)), "l"(gp) : "memory")
#define CP_COMMIT() asm volatile("cp.async.commit_group;" ::: "memory")
#define CP_WAIT2()  asm volatile("cp.async.wait_group 2;" ::: "memory")

__device__ __forceinline__ void ldsm4(uint32_t r[4], uint32_t a) {
    asm volatile("ldmatrix.sync.aligned.m8n8.x4.shared.b16 {%0,%1,%2,%3}, [%4];"
                 : "=r"(r[0]), "=r"(r[1]), "=r"(r[2]), "=r"(r[3]) : "r"(a));
}
__device__ __forceinline__ void mma16816(float c[4],
                                         const uint32_t a[4],
                                         uint32_t b0, uint32_t b1) {
    asm volatile(
        "mma.sync.aligned.m16n8k16.row.col.f32.f16.f16.f32 "
        "{%0,%1,%2,%3}, {%4,%5,%6,%7}, {%8,%9}, {%0,%1,%2,%3};"
        : "+f"(c[0]), "+f"(c[1]), "+f"(c[2]), "+f"(c[3])
        : "r"(a[0]), "r"(a[1]), "r"(a[2]), "r"(a[3]), "r"(b0), "r"(b1));
}

__device__ __forceinline__ void store_h4(__half* p, float4 v) {
    __half2 a = __floats2half2_rn(v.x, v.y);
    __half2 b = __floats2half2_rn(v.z, v.w);
    uint2 u;
    u.x = *(uint32_t*)&a;
    u.y = *(uint32_t*)&b;
    *(uint2*)p = u;
}

// ---------------------------------------------------------------------------
// Kernel 0 (prep): transpose pw_kernel -> g_b [n][k] fp16; zero counters.
// ---------------------------------------------------------------------------
__global__ void __launch_bounds__(256) prep_kernel(const float* __restrict__ pwk) {
    const int t = threadIdx.x;
    const int idx = blockIdx.x * 256 + t;  // 65536 total
    const int k = idx >> 8, n = idx & 255;
    g_b[(size_t)n * CC + k] = __float2half_rn(pwk[(size_t)k * CC + n]);
    if (blockIdx.x == 0)
        for (int i = t; i < SEGS; i += 256) g_cnt[i] = 0;
}

// ---------------------------------------------------------------------------
// Fused kernel, interleaved, 3 CTAs/SM (reg cap via __launch_bounds__(256,3)).
// Group g (12 blocks): role 0..7  -> dw block (16 px) of segment g;
//                      role 8..11 -> gemm block (bn = (role-8)*64) of seg g-LAG.
// dw: 4 px/thread (col[8], acc[4]) to fit the reg cap.
// gemm: CTA 128x64, 8 warps 4m x 2n, warp tile 32x32, 4-stage cp.async,
//       B frags up front + A ldsm pipelined one step ahead.
// ---------------------------------------------------------------------------
#define STRIDE 80
#define A_TILE (128 * STRIDE)          // 10240
#define B_TILE (64 * STRIDE)           // 5120
#define OFF_BSM A_TILE
#define STAGE_B (A_TILE + B_TILE)      // 15360
#define OFF_INV (4 * STAGE_B)          // 61440
#define OFF_B2  (OFF_INV + 256)
#define SMEM_BYTES (OFF_B2 + 256)      // 61952 -> 3 CTAs/SM smem-ok

__global__ void __launch_bounds__(256, 3) fused_kernel(
    const float* __restrict__ x,
    const float* __restrict__ dwk,
    const float* __restrict__ dwb,
    const float* __restrict__ pwb,
    const float* __restrict__ gma,
    const float* __restrict__ bta,
    const float* __restrict__ mmean,
    const float* __restrict__ mvar,
    float* __restrict__ out)
{
    extern __shared__ __align__(128) char smem[];
    const int t = threadIdx.x;
    const int grp = blockIdx.x / 12;
    const int role = blockIdx.x % 12;

    if (role < 8) {
        // ------------------------- depthwise path -------------------------
        if (grp >= SEGS) return;
        const int dwb_id = grp * 8 + role;             // dw block id 0..6271
        const int c = (t & 63) * 4;                    // channel group (4 ch)
        const int q = dwb_id * 4 + (t >> 6);           // quad id 0..25087
        const int w0 = (q % 14) * 4;
        const int nh = q / 14;
        const int h = nh % HH;
        const int n = nh / HH;

        const float4 bias = *(const float4*)(dwb + c);

        float4 acc[4];
#pragma unroll
        for (int px = 0; px < 4; px++) acc[px] = bias;

#pragma unroll
        for (int kh = 0; kh < 3; kh++) {
            const int hh = h + 2 * kh - 2;
            if ((unsigned)hh >= (unsigned)HH) continue;
            const float* xrow = x + ((size_t)(n * HH + hh) * WW) * CC + c;

            const float4 k0 = *(const float4*)(dwk + (kh * 3 + 0) * CC + c);
            const float4 k1 = *(const float4*)(dwk + (kh * 3 + 1) * CC + c);
            const float4 k2 = *(const float4*)(dwk + (kh * 3 + 2) * CC + c);

            float4 col[8];
#pragma unroll
            for (int j = 0; j < 8; j++) {
                const int ww = w0 - 2 + j;
                if ((unsigned)ww < (unsigned)WW) {
                    float4 v = *(const float4*)(xrow + (size_t)ww * CC);
                    v.x = fmaxf(v.x, 0.0f); v.y = fmaxf(v.y, 0.0f);
                    v.z = fmaxf(v.z, 0.0f); v.w = fmaxf(v.w, 0.0f);
                    col[j] = v;
                } else {
                    col[j] = make_float4(0.f, 0.f, 0.f, 0.f);
                }
            }
#pragma unroll
            for (int px = 0; px < 4; px++) {
                acc[px].x = fmaf(col[px].x, k0.x, fmaf(col[px + 2].x, k1.x, fmaf(col[px + 4].x, k2.x, acc[px].x)));
                acc[px].y = fmaf(col[px].y, k0.y, fmaf(col[px + 2].y, k1.y, fmaf(col[px + 4].y, k2.y, acc[px].y)));
                acc[px].z = fmaf(col[px].z, k0.z, fmaf(col[px + 2].z, k1.z, fmaf(col[px + 4].z, k2.z, acc[px].z)));
                acc[px].w = fmaf(col[px].w, k0.w, fmaf(col[px + 2].w, k1.w, fmaf(col[px + 4].w, k2.w, acc[px].w)));
            }
        }

        const size_t base = ((size_t)(n * HH + h) * WW + w0) * CC + c;
#pragma unroll
        for (int px = 0; px < 4; px++)
            store_h4(g_a + base + (size_t)px * CC, acc[px]);

        // release: all stores visible, then signal segment readiness
        __threadfence();
        __syncthreads();
        if (t == 0) atomicAdd(&g_cnt[grp], 1);
        return;
    }

    // ----------------------------- GEMM path -----------------------------
    const int seg = grp - LAG;
    if (seg < 0) return;
    const uint32_t sb = smem_u32(smem);
    const int lane = t & 31, wid = t >> 5;
    const int wm = wid & 3, wn = wid >> 2;   // 4m x 2n, warp tile 32x32
    const int r = lane >> 2, tg = lane & 3;
    const int bn = (role - 8) * 64;
    const int bm = seg * 128;

    // BN constants (64 columns of this CTA)
    float* sinv = (float*)(smem + OFF_INV);
    float* sbb  = (float*)(smem + OFF_B2);
    if (t < 64) {
        const int nn = bn + t;
        const float iv = gma[nn] * rsqrtf(mvar[nn] + 1e-3f);
        sinv[t] = iv;
        sbb[t]  = fmaf(pwb[nn], iv, bta[nn] - mmean[nn] * iv);
    }

    // acquire-spin until this segment's 8 dw blocks have finished (rare)
    if (t == 0) {
        int v;
        do {
            asm volatile("ld.global.acquire.gpu.b32 %0, [%1];"
                         : "=r"(v) : "l"(g_cnt + seg) : "memory");
            if (v != 8) __nanosleep(128);
        } while (v != 8);
    }
    __syncthreads();

    // loaders: A (128 rows x 64B): all threads, row t>>1, half t&1 (2 cp16)
    //          B (64 rows x 64B): threads <128, row t>>1, half t&1 (2 cp16)
    const __half* gA = g_a + (size_t)(bm + (t >> 1)) * CC + (t & 1) * 16;
    const __half* gB = g_b + (size_t)(bn + (t >> 1)) * CC + (t & 1) * 16;
    const uint32_t sdA = sb + (t >> 1) * STRIDE + (t & 1) * 32;
    const uint32_t sdB = sb + OFF_BSM + (t >> 1) * STRIDE + (t & 1) * 32;
    const bool doB = (t < 128);

#define ISSUE(k0, stoff) do {                                               \
    CP16(sdA + (stoff) + 0,   gA + (k0));                                   \
    CP16(sdA + (stoff) + 16,  gA + (k0) + 8);                               \
    if (doB) {                                                              \
        CP16(sdB + (stoff) + 0,   gB + (k0));                               \
        CP16(sdB + (stoff) + 16,  gB + (k0) + 8);                           \
    }                                                                       \
    CP_COMMIT();                                                            \
} while (0)

    // prologue: stages 0..2
    ISSUE(0, 0);
    ISSUE(32, STAGE_B);
    ISSUE(64, 2 * STAGE_B);

    float acc[2][4][4];
#pragma unroll
    for (int mt = 0; mt < 2; mt++)
#pragma unroll
        for (int nt = 0; nt < 4; nt++)
#pragma unroll
            for (int i = 0; i < 4; i++) acc[mt][nt][i] = 0.0f;

    // ldmatrix lane addresses (offsets within a stage)
    const uint32_t aAddr = sb + (wm * 32 + (lane & 15)) * STRIDE + (lane >> 4) * 16;
    const uint32_t bAddr = sb + OFF_BSM +
        (wn * 32 + ((lane >> 4) << 3) + (lane & 7)) * STRIDE + ((lane >> 3) & 1) * 16;

    uint32_t st = 0;                 // compute-stage byte offset
    uint32_t ist = 3 * STAGE_B;      // issue-stage byte offset

    for (int c = 0; c < 8; c++) {
        CP_WAIT2();                  // stage c complete (<=2 groups pending)
        __syncthreads();             // visibility + protects buffer reuse
        if (c < 5) {
            ISSUE((c + 3) * 32, ist);
            ist = (ist == 3 * STAGE_B) ? 0u : ist + STAGE_B;
        } else {
            CP_COMMIT();             // keep group counting aligned
        }

        // B fragments for both k16 halves of this chunk (4 ldsm.x4, 16 regs)
        uint32_t bf[2][2][4];
#pragma unroll
        for (int k16 = 0; k16 < 2; k16++)
#pragma unroll
            for (int np = 0; np < 2; np++)
                ldsm4(bf[k16][np], bAddr + st + np * (16 * STRIDE) + k16 * 32);

        // A fragments pipelined one (k16, mt) step ahead
        uint32_t acur[4], anxt[4];
        ldsm4(acur, aAddr + st);     // (k16=0, mt=0)
#pragma unroll
        for (int s = 0; s < 4; s++) {
            const int k16 = s >> 1, mt = s & 1;
            if (s < 3) {
                const int s2 = s + 1;
                ldsm4(anxt, aAddr + st + (s2 & 1) * (16 * STRIDE) + (s2 >> 1) * 32);
            }
#pragma unroll
            for (int np = 0; np < 2; np++) {
#pragma unroll
                for (int half = 0; half < 2; half++) {
                    mma16816(acc[mt][np * 2 + half], acur,
                             bf[k16][np][half * 2], bf[k16][np][half * 2 + 1]);
                }
            }
#pragma unroll
            for (int i = 0; i < 4; i++) acur[i] = anxt[i];
        }
        st = (st == 3 * STAGE_B) ? 0u : st + STAGE_B;
    }

    // Epilogue: BN scale/offset + store
#pragma unroll
    for (int mt = 0; mt < 2; mt++) {
        const int row0 = bm + wm * 32 + mt * 16 + r;
#pragma unroll
        for (int nt = 0; nt < 4; nt++) {
            const int cl = wn * 32 + nt * 8 + tg * 2;   // local col 0..63
            const float i0 = sinv[cl], i1 = sinv[cl + 1];
            const float o0 = sbb[cl],  o1 = sbb[cl + 1];
            float2 v0, v1;
            v0.x = fmaf(acc[mt][nt][0], i0, o0);
            v0.y = fmaf(acc[mt][nt][1], i1, o1);
            v1.x = fmaf(acc[mt][nt][2], i0, o0);
            v1.y = fmaf(acc[mt][nt][3], i1, o1);
            *(float2*)(out + (size_t)row0 * CC + bn + cl)       = v0;
            *(float2*)(out + (size_t)(row0 + 8) * CC + bn + cl) = v1;
        }
    }
#undef ISSUE
}

// ---------------------------------------------------------------------------
// Launch
// ---------------------------------------------------------------------------
extern "C" void kernel_launch(void* const* d_in, const int* in_sizes, int n_in,
                              void* d_out, int out_size)
{
    const float* x     = (const float*)d_in[0];
    const float* dwk   = (const float*)d_in[1];
    const float* dwb   = (const float*)d_in[2];
    const float* pwk   = (const float*)d_in[3];
    const float* pwb   = (const float*)d_in[4];
    const float* gma   = (const float*)d_in[5];
    const float* bta   = (const float*)d_in[6];
    const float* mmean = (const float*)d_in[7];
    const float* mvar  = (const float*)d_in[8];
    float* out = (float*)d_out;

    static int smem_set = 0;
    if (!smem_set) {
        cudaFuncSetAttribute(fused_kernel,
                             cudaFuncAttributeMaxDynamicSharedMemorySize, SMEM_BYTES);
        smem_set = 1;
    }

    prep_kernel<<<256, 256>>>(pwk);
    fused_kernel<<<TOTAL_BLOCKS, 256, SMEM_BYTES>>>(
        x, dwk, dwb, pwb, gma, bta, mmean, mvar, out);
}

// round 15
// speedup vs baseline: 1.1892x; 1.1755x over previous
#include <cuda_runtime.h>
#include <cuda_fp16.h>
#include <cstdint>

// Problem constants
#define NN 32
#define HH 56
#define WW 56
#define CC 256
#define PP (NN * HH * WW)   // 100352 pixels

#define SEGS 784            // 128-pixel segments
#define LAG 112             // gemm trails dw by LAG groups (672 blocks > window)
#define GROUPS (SEGS + LAG) // 896
#define TOTAL_BLOCKS (GROUPS * 6)   // 5376

// ---------------------------------------------------------------------------
// Scratch: dw output fp16, transposed fp16 weights, per-segment ready counters.
// ---------------------------------------------------------------------------
__device__ __align__(256) __half g_a[(size_t)PP * CC];
__device__ __align__(256) __half g_b[CC * CC];
__device__ int g_cnt[SEGS];

// ---------------------------------------------------------------------------
// PTX helpers
// ---------------------------------------------------------------------------
__device__ __forceinline__ uint32_t smem_u32(const void* p) {
    uint32_t a;
    asm("{ .reg .u64 t; cvta.to.shared.u64 t, %1; cvt.u32.u64 %0, t; }"
        : "=r"(a) : "l"(p));
    return a;
}
#define CP16(sa, gp) \
    asm volatile("cp.async.cg.shared.global [%0], [%1], 16;" \
                 :: "r"((uint32_t)(sa)), "l"(gp) : "memory")
#define CP_COMMIT() asm volatile("cp.async.commit_group;" ::: "memory")
#define CP_WAIT0()  asm volatile("cp.async.wait_group 0;" ::: "memory")

__device__ __forceinline__ void ldsm4(uint32_t r[4], uint32_t a) {
    asm volatile("ldmatrix.sync.aligned.m8n8.x4.shared.b16 {%0,%1,%2,%3}, [%4];"
                 : "=r"(r[0]), "=r"(r[1]), "=r"(r[2]), "=r"(r[3]) : "r"(a));
}
__device__ __forceinline__ void mma16816(float c[4],
                                         const uint32_t a[4],
                                         uint32_t b0, uint32_t b1) {
    asm volatile(
        "mma.sync.aligned.m16n8k16.row.col.f32.f16.f16.f32 "
        "{%0,%1,%2,%3}, {%4,%5,%6,%7}, {%8,%9}, {%0,%1,%2,%3};"
        : "+f"(c[0]), "+f"(c[1]), "+f"(c[2]), "+f"(c[3])
        : "r"(a[0]), "r"(a[1]), "r"(a[2]), "r"(a[3]), "r"(b0), "r"(b1));
}

__device__ __forceinline__ void store_h4(__half* p, float4 v) {
    __half2 a = __floats2half2_rn(v.x, v.y);
    __half2 b = __floats2half2_rn(v.z, v.w);
    uint2 u;
    u.x = *(uint32_t*)&a;
    u.y = *(uint32_t*)&b;
    *(uint2*)p = u;
}

// ---------------------------------------------------------------------------
// Kernel 0 (prep): transpose pw_kernel -> g_b [n][k] fp16; zero counters.
// ---------------------------------------------------------------------------
__global__ void __launch_bounds__(256) prep_kernel(const float* __restrict__ pwk) {
    const int t = threadIdx.x;
    const int idx = blockIdx.x * 256 + t;  // 65536 total
    const int k = idx >> 8, n = idx & 255;
    g_b[(size_t)n * CC + k] = __float2half_rn(pwk[(size_t)k * CC + n]);
    if (blockIdx.x == 0)
        for (int i = t; i < SEGS; i += 256) g_cnt[i] = 0;
}

// ---------------------------------------------------------------------------
// Fused kernel (R12 structure), GEMM upgraded to K=64 macro-chunks:
// one barrier per 2 stages; all 8 B-frag ldsm up front; A pipelined
// through 16 MMA steps. 4 barriers total instead of 8.
// Group g (6 blocks): role 0..3 -> dw of segment g (if g < SEGS);
//                     role 4..5 -> gemm (bn = role-4) of segment g-LAG.
// ---------------------------------------------------------------------------
#define STRIDE 80
#define A_TILE (128 * STRIDE)          // 10240
#define B_TILE (128 * STRIDE)          // 10240
#define OFF_BSM A_TILE
#define STAGE_B (A_TILE + B_TILE)      // 20480
#define OFF_INV (4 * STAGE_B)          // 81920
#define OFF_B2  (OFF_INV + 512)
#define SMEM_BYTES (OFF_B2 + 512)      // 82944

__global__ void __launch_bounds__(256, 2) fused_kernel(
    const float* __restrict__ x,
    const float* __restrict__ dwk,
    const float* __restrict__ dwb,
    const float* __restrict__ pwb,
    const float* __restrict__ gma,
    const float* __restrict__ bta,
    const float* __restrict__ mmean,
    const float* __restrict__ mvar,
    float* __restrict__ out)
{
    extern __shared__ __align__(128) char smem[];
    const int t = threadIdx.x;
    const int grp = blockIdx.x / 6;
    const int role = blockIdx.x % 6;

    if (role < 4) {
        // ------------------------- depthwise path -------------------------
        if (grp >= SEGS) return;
        const int dwb_id = grp * 4 + role;             // dw block id 0..3135
        const int c = (t & 63) * 4;                    // channel group
        const int oct = dwb_id * 4 + (t >> 6);         // 0..12543
        const int w0 = (oct % 7) * 8;
        const int nh = oct / 7;
        const int h = nh % HH;
        const int n = nh / HH;

        const float4 bias = *(const float4*)(dwb + c);

        float4 acc[8];
#pragma unroll
        for (int px = 0; px < 8; px++) acc[px] = bias;

#pragma unroll
        for (int kh = 0; kh < 3; kh++) {
            const int hh = h + 2 * kh - 2;
            if ((unsigned)hh >= (unsigned)HH) continue;
            const float* xrow = x + ((size_t)(n * HH + hh) * WW) * CC + c;

            const float4 k0 = *(const float4*)(dwk + (kh * 3 + 0) * CC + c);
            const float4 k1 = *(const float4*)(dwk + (kh * 3 + 1) * CC + c);
            const float4 k2 = *(const float4*)(dwk + (kh * 3 + 2) * CC + c);

            float4 col[12];
#pragma unroll
            for (int j = 0; j < 12; j++) {
                const int ww = w0 - 2 + j;
                if ((unsigned)ww < (unsigned)WW) {
                    float4 v = *(const float4*)(xrow + (size_t)ww * CC);
                    v.x = fmaxf(v.x, 0.0f); v.y = fmaxf(v.y, 0.0f);
                    v.z = fmaxf(v.z, 0.0f); v.w = fmaxf(v.w, 0.0f);
                    col[j] = v;
                } else {
                    col[j] = make_float4(0.f, 0.f, 0.f, 0.f);
                }
            }
#pragma unroll
            for (int px = 0; px < 8; px++) {
                acc[px].x = fmaf(col[px].x, k0.x, fmaf(col[px + 2].x, k1.x, fmaf(col[px + 4].x, k2.x, acc[px].x)));
                acc[px].y = fmaf(col[px].y, k0.y, fmaf(col[px + 2].y, k1.y, fmaf(col[px + 4].y, k2.y, acc[px].y)));
                acc[px].z = fmaf(col[px].z, k0.z, fmaf(col[px + 2].z, k1.z, fmaf(col[px + 4].z, k2.z, acc[px].z)));
                acc[px].w = fmaf(col[px].w, k0.w, fmaf(col[px + 2].w, k1.w, fmaf(col[px + 4].w, k2.w, acc[px].w)));
            }
        }

        const size_t base = ((size_t)(n * HH + h) * WW + w0) * CC + c;
#pragma unroll
        for (int px = 0; px < 8; px++)
            store_h4(g_a + base + (size_t)px * CC, acc[px]);

        // release: all stores visible, then signal segment readiness
        __threadfence();
        __syncthreads();
        if (t == 0) atomicAdd(&g_cnt[grp], 1);
        return;
    }

    // ----------------------------- GEMM path -----------------------------
    const int seg = grp - LAG;
    if (seg < 0) return;
    const uint32_t sb = smem_u32(smem);
    const int lane = t & 31, wid = t >> 5;
    const int wm = wid & 1, wn = wid >> 1;   // 2m x 4n, warp tile 64x32
    const int r = lane >> 2, tg = lane & 3;
    const int bn = (role - 4) * 128;
    const int bm = seg * 128;

    // BN constants
    float* sinv = (float*)(smem + OFF_INV);
    float* sbb  = (float*)(smem + OFF_B2);
    if (t < 128) {
        const int nn = bn + t;
        const float iv = gma[nn] * rsqrtf(mvar[nn] + 1e-3f);
        sinv[t] = iv;
        sbb[t]  = fmaf(pwb[nn], iv, bta[nn] - mmean[nn] * iv);
    }

    // acquire-spin until this segment's 4 dw blocks have finished (rare)
    if (t == 0) {
        int v;
        do {
            asm volatile("ld.global.acquire.gpu.b32 %0, [%1];"
                         : "=r"(v) : "l"(g_cnt + seg) : "memory");
            if (v != 4) __nanosleep(128);
        } while (v != 4);
    }
    __syncthreads();

    // loaders: thread t -> row t>>1, 32B half t&1 (2 cp16 each for A and B)
    const __half* gA = g_a + (size_t)(bm + (t >> 1)) * CC + (t & 1) * 16;
    const __half* gB = g_b + (size_t)(bn + (t >> 1)) * CC + (t & 1) * 16;
    const uint32_t sdA = sb + (t >> 1) * STRIDE + (t & 1) * 32;
    const uint32_t sdB = sb + OFF_BSM + (t >> 1) * STRIDE + (t & 1) * 32;

#define ISSUE(k0, stoff) do {                                               \
    CP16(sdA + (stoff) + 0,   gA + (k0));                                   \
    CP16(sdA + (stoff) + 16,  gA + (k0) + 8);                               \
    CP16(sdB + (stoff) + 0,   gB + (k0));                                   \
    CP16(sdB + (stoff) + 16,  gB + (k0) + 8);                               \
    CP_COMMIT();                                                            \
} while (0)

    // prologue: stages 0,1 (buffers 0,1)
    ISSUE(0, 0);
    ISSUE(32, STAGE_B);

    float acc[4][4][4];
#pragma unroll
    for (int mt = 0; mt < 4; mt++)
#pragma unroll
        for (int nt = 0; nt < 4; nt++)
#pragma unroll
            for (int i = 0; i < 4; i++) acc[mt][nt][i] = 0.0f;

    // ldmatrix lane addresses (offsets within a stage)
    const uint32_t aAddr = sb + (wm * 64 + (lane & 15)) * STRIDE + (lane >> 4) * 16;
    const uint32_t bAddr = sb + OFF_BSM +
        (wn * 32 + ((lane >> 4) << 3) + (lane & 7)) * STRIDE + ((lane >> 3) & 1) * 16;

    // 4 macro-chunks of K=64 (stage pair per macro-chunk), ONE barrier each.
    for (int mc = 0; mc < 4; mc++) {
        CP_WAIT0();                  // both stages of this pair complete
        __syncthreads();             // all warps done reading the other pair
        if (mc < 3) {                // refill the other pair (buffers free now)
            const uint32_t ipair = (uint32_t)(((mc + 1) & 1) * (2 * STAGE_B));
            ISSUE((2 * mc + 2) * 32, ipair);
            ISSUE((2 * mc + 3) * 32, ipair + STAGE_B);
        }

        const uint32_t st0 = (uint32_t)((mc & 1) * (2 * STAGE_B));

        // all B fragments for both chunks of this macro-chunk (8 ldsm.x4)
        uint32_t bf[2][2][2][4];     // [chunk][k16][np][4]
#pragma unroll
        for (int ck = 0; ck < 2; ck++)
#pragma unroll
            for (int k16 = 0; k16 < 2; k16++)
#pragma unroll
                for (int np = 0; np < 2; np++)
                    ldsm4(bf[ck][k16][np],
                          bAddr + st0 + ck * STAGE_B + np * (16 * STRIDE) + k16 * 32);

        // A fragments pipelined one step ahead through 16 MMA steps
        uint32_t acur[4], anxt[4];
        ldsm4(acur, aAddr + st0);    // (ck0, k16=0, mt0)
#pragma unroll
        for (int s = 0; s < 16; s++) {
            const int ck = s >> 3, k16 = (s >> 2) & 1, mt = s & 3;
            if (s < 15) {
                const int s2 = s + 1;
                ldsm4(anxt, aAddr + st0 + (s2 >> 3) * STAGE_B
                                    + ((s2 >> 2) & 1) * 32
                                    + (s2 & 3) * (16 * STRIDE));
            }
#pragma unroll
            for (int np = 0; np < 2; np++) {
#pragma unroll
                for (int half = 0; half < 2; half++) {
                    mma16816(acc[mt][np * 2 + half], acur,
                             bf[ck][k16][np][half * 2], bf[ck][k16][np][half * 2 + 1]);
                }
            }
#pragma unroll
            for (int i = 0; i < 4; i++) acur[i] = anxt[i];
        }
    }

    // Epilogue: BN scale/offset + store
#pragma unroll
    for (int mt = 0; mt < 4; mt++) {
        const int row0 = bm + wm * 64 + mt * 16 + r;
#pragma unroll
        for (int nt = 0; nt < 4; nt++) {
            const int cl = wn * 32 + nt * 8 + tg * 2;   // local col 0..127
            const float i0 = sinv[cl], i1 = sinv[cl + 1];
            const float o0 = sbb[cl],  o1 = sbb[cl + 1];
            float2 v0, v1;
            v0.x = fmaf(acc[mt][nt][0], i0, o0);
            v0.y = fmaf(acc[mt][nt][1], i1, o1);
            v1.x = fmaf(acc[mt][nt][2], i0, o0);
            v1.y = fmaf(acc[mt][nt][3], i1, o1);
            *(float2*)(out + (size_t)row0 * CC + bn + cl)       = v0;
            *(float2*)(out + (size_t)(row0 + 8) * CC + bn + cl) = v1;
        }
    }
#undef ISSUE
}

// ---------------------------------------------------------------------------
// Launch
// ---------------------------------------------------------------------------
extern "C" void kernel_launch(void* const* d_in, const int* in_sizes, int n_in,
                              void* d_out, int out_size)
{
    const float* x     = (const float*)d_in[0];
    const float* dwk   = (const float*)d_in[1];
    const float* dwb   = (const float*)d_in[2];
    const float* pwk   = (const float*)d_in[3];
    const float* pwb   = (const float*)d_in[4];
    const float* gma   = (const float*)d_in[5];
    const float* bta   = (const float*)d_in[6];
    const float* mmean = (const float*)d_in[7];
    const float* mvar  = (const float*)d_in[8];
    float* out = (float*)d_out;

    static int smem_set = 0;
    if (!smem_set) {
        cudaFuncSetAttribute(fused_kernel,
                             cudaFuncAttributeMaxDynamicSharedMemorySize, SMEM_BYTES);
        smem_set = 1;
    }

    prep_kernel<<<256, 256>>>(pwk);
    fused_kernel<<<TOTAL_BLOCKS, 256, SMEM_BYTES>>>(
        x, dwk, dwb, pwb, gma, bta, mmean, mvar, out);
}

// round 16
// speedup vs baseline: 1.2461x; 1.0478x over previous
#include <cuda_runtime.h>
#include <cuda_fp16.h>
#include <cstdint>

// Problem constants
#define NN 32
#define HH 56
#define WW 56
#define CC 256
#define PP (NN * HH * WW)   // 100352 pixels

#define SEGS 784            // 128-pixel segments
#define LAG 72              // gemm trails dw by LAG groups (432 blocks, ~1.45x window)
#define GROUPS (SEGS + LAG) // 856
#define TOTAL_BLOCKS (GROUPS * 6)   // 5136

// ---------------------------------------------------------------------------
// Scratch: dw output fp16, transposed fp16 weights, per-segment ready counters.
// ---------------------------------------------------------------------------
__device__ __align__(256) __half g_a[(size_t)PP * CC];
__device__ __align__(256) __half g_b[CC * CC];
__device__ int g_cnt[SEGS];

// ---------------------------------------------------------------------------
// PTX helpers
// ---------------------------------------------------------------------------
__device__ __forceinline__ uint32_t smem_u32(const void* p) {
    uint32_t a;
    asm("{ .reg .u64 t; cvta.to.shared.u64 t, %1; cvt.u32.u64 %0, t; }"
        : "=r"(a) : "l"(p));
    return a;
}
#define CP16(sa, gp) \
    asm volatile("cp.async.cg.shared.global [%0], [%1], 16;" \
                 :: "r"((uint32_t)(sa)), "l"(gp) : "memory")
#define CP_COMMIT() asm volatile("cp.async.commit_group;" ::: "memory")
#define CP_WAIT2()  asm volatile("cp.async.wait_group 2;" ::: "memory")

__device__ __forceinline__ void ldsm4(uint32_t r[4], uint32_t a) {
    asm volatile("ldmatrix.sync.aligned.m8n8.x4.shared.b16 {%0,%1,%2,%3}, [%4];"
                 : "=r"(r[0]), "=r"(r[1]), "=r"(r[2]), "=r"(r[3]) : "r"(a));
}
__device__ __forceinline__ void mma16816(float c[4],
                                         const uint32_t a[4],
                                         uint32_t b0, uint32_t b1) {
    asm volatile(
        "mma.sync.aligned.m16n8k16.row.col.f32.f16.f16.f32 "
        "{%0,%1,%2,%3}, {%4,%5,%6,%7}, {%8,%9}, {%0,%1,%2,%3};"
        : "+f"(c[0]), "+f"(c[1]), "+f"(c[2]), "+f"(c[3])
        : "r"(a[0]), "r"(a[1]), "r"(a[2]), "r"(a[3]), "r"(b0), "r"(b1));
}

__device__ __forceinline__ void store_h4(__half* p, float4 v) {
    __half2 a = __floats2half2_rn(v.x, v.y);
    __half2 b = __floats2half2_rn(v.z, v.w);
    uint2 u;
    u.x = *(uint32_t*)&a;
    u.y = *(uint32_t*)&b;
    *(uint2*)p = u;
}

// ---------------------------------------------------------------------------
// Kernel 0 (prep): transpose pw_kernel -> g_b [n][k] fp16; zero counters.
// ---------------------------------------------------------------------------
__global__ void __launch_bounds__(256) prep_kernel(const float* __restrict__ pwk) {
    const int t = threadIdx.x;
    const int idx = blockIdx.x * 256 + t;  // 65536 total
    const int k = idx >> 8, n = idx & 255;
    g_b[(size_t)n * CC + k] = __float2half_rn(pwk[(size_t)k * CC + n]);
    if (blockIdx.x == 0)
        for (int i = t; i < SEGS; i += 256) g_cnt[i] = 0;
}

// ---------------------------------------------------------------------------
// Fused kernel (R12 structure, tuned edges).
// Group g (6 blocks): role 0..3 -> dw of segment g (if g < SEGS);
//                     role 4..5 -> gemm (bn = role-4) of segment g-LAG.
// dw release uses red.release.gpu after __syncthreads (no full threadfence).
// ---------------------------------------------------------------------------
#define STRIDE 80
#define A_TILE (128 * STRIDE)          // 10240
#define B_TILE (128 * STRIDE)          // 10240
#define OFF_BSM A_TILE
#define STAGE_B (A_TILE + B_TILE)      // 20480
#define OFF_INV (4 * STAGE_B)          // 81920
#define OFF_B2  (OFF_INV + 512)
#define SMEM_BYTES (OFF_B2 + 512)      // 82944

__global__ void __launch_bounds__(256, 2) fused_kernel(
    const float* __restrict__ x,
    const float* __restrict__ dwk,
    const float* __restrict__ dwb,
    const float* __restrict__ pwb,
    const float* __restrict__ gma,
    const float* __restrict__ bta,
    const float* __restrict__ mmean,
    const float* __restrict__ mvar,
    float* __restrict__ out)
{
    extern __shared__ __align__(128) char smem[];
    const int t = threadIdx.x;
    const int grp = blockIdx.x / 6;
    const int role = blockIdx.x % 6;

    if (role < 4) {
        // ------------------------- depthwise path -------------------------
        if (grp >= SEGS) return;
        const int dwb_id = grp * 4 + role;             // dw block id 0..3135
        const int c = (t & 63) * 4;                    // channel group
        const int oct = dwb_id * 4 + (t >> 6);         // 0..12543
        const int w0 = (oct % 7) * 8;
        const int nh = oct / 7;
        const int h = nh % HH;
        const int n = nh / HH;

        const float4 bias = *(const float4*)(dwb + c);

        float4 acc[8];
#pragma unroll
        for (int px = 0; px < 8; px++) acc[px] = bias;

#pragma unroll
        for (int kh = 0; kh < 3; kh++) {
            const int hh = h + 2 * kh - 2;
            if ((unsigned)hh >= (unsigned)HH) continue;
            const float* xrow = x + ((size_t)(n * HH + hh) * WW) * CC + c;

            const float4 k0 = *(const float4*)(dwk + (kh * 3 + 0) * CC + c);
            const float4 k1 = *(const float4*)(dwk + (kh * 3 + 1) * CC + c);
            const float4 k2 = *(const float4*)(dwk + (kh * 3 + 2) * CC + c);

            float4 col[12];
#pragma unroll
            for (int j = 0; j < 12; j++) {
                const int ww = w0 - 2 + j;
                if ((unsigned)ww < (unsigned)WW) {
                    float4 v = *(const float4*)(xrow + (size_t)ww * CC);
                    v.x = fmaxf(v.x, 0.0f); v.y = fmaxf(v.y, 0.0f);
                    v.z = fmaxf(v.z, 0.0f); v.w = fmaxf(v.w, 0.0f);
                    col[j] = v;
                } else {
                    col[j] = make_float4(0.f, 0.f, 0.f, 0.f);
                }
            }
#pragma unroll
            for (int px = 0; px < 8; px++) {
                acc[px].x = fmaf(col[px].x, k0.x, fmaf(col[px + 2].x, k1.x, fmaf(col[px + 4].x, k2.x, acc[px].x)));
                acc[px].y = fmaf(col[px].y, k0.y, fmaf(col[px + 2].y, k1.y, fmaf(col[px + 4].y, k2.y, acc[px].y)));
                acc[px].z = fmaf(col[px].z, k0.z, fmaf(col[px + 2].z, k1.z, fmaf(col[px + 4].z, k2.z, acc[px].z)));
                acc[px].w = fmaf(col[px].w, k0.w, fmaf(col[px + 2].w, k1.w, fmaf(col[px + 4].w, k2.w, acc[px].w)));
            }
        }

        const size_t base = ((size_t)(n * HH + h) * WW + w0) * CC + c;
#pragma unroll
        for (int px = 0; px < 8; px++)
            store_h4(g_a + base + (size_t)px * CC, acc[px]);

        // release: barrier gives CTA-wide happens-before over the stores;
        // the release-reduction transfers it GPU-scope (no full membar).
        __syncthreads();
        if (t == 0)
            asm volatile("red.release.gpu.global.add.s32 [%0], %1;"
                         :: "l"(g_cnt + grp), "r"(1) : "memory");
        return;
    }

    // ----------------------------- GEMM path -----------------------------
    const int seg = grp - LAG;
    if (seg < 0) return;
    const uint32_t sb = smem_u32(smem);
    const int lane = t & 31, wid = t >> 5;
    const int wm = wid & 1, wn = wid >> 1;   // 2m x 4n, warp tile 64x32
    const int r = lane >> 2, tg = lane & 3;
    const int bn = (role - 4) * 128;
    const int bm = seg * 128;

    // BN constants
    float* sinv = (float*)(smem + OFF_INV);
    float* sbb  = (float*)(smem + OFF_B2);
    if (t < 128) {
        const int nn = bn + t;
        const float iv = gma[nn] * rsqrtf(mvar[nn] + 1e-3f);
        sinv[t] = iv;
        sbb[t]  = fmaf(pwb[nn], iv, bta[nn] - mmean[nn] * iv);
    }

    // acquire-spin until this segment's 4 dw blocks have finished (rare)
    if (t == 0) {
        int v;
        do {
            asm volatile("ld.global.acquire.gpu.b32 %0, [%1];"
                         : "=r"(v) : "l"(g_cnt + seg) : "memory");
            if (v != 4) __nanosleep(128);
        } while (v != 4);
    }
    __syncthreads();

    // loaders: thread t -> row t>>1, 32B half t&1 (2 cp16 each for A and B)
    const __half* gA = g_a + (size_t)(bm + (t >> 1)) * CC + (t & 1) * 16;
    const __half* gB = g_b + (size_t)(bn + (t >> 1)) * CC + (t & 1) * 16;
    const uint32_t sdA = sb + (t >> 1) * STRIDE + (t & 1) * 32;
    const uint32_t sdB = sb + OFF_BSM + (t >> 1) * STRIDE + (t & 1) * 32;

#define ISSUE(k0, stoff) do {                                               \
    CP16(sdA + (stoff) + 0,   gA + (k0));                                   \
    CP16(sdA + (stoff) + 16,  gA + (k0) + 8);                               \
    CP16(sdB + (stoff) + 0,   gB + (k0));                                   \
    CP16(sdB + (stoff) + 16,  gB + (k0) + 8);                               \
    CP_COMMIT();                                                            \
} while (0)

    // prologue: stages 0..2
    ISSUE(0, 0);
    ISSUE(32, STAGE_B);
    ISSUE(64, 2 * STAGE_B);

    float acc[4][4][4];
#pragma unroll
    for (int mt = 0; mt < 4; mt++)
#pragma unroll
        for (int nt = 0; nt < 4; nt++)
#pragma unroll
            for (int i = 0; i < 4; i++) acc[mt][nt][i] = 0.0f;

    // ldmatrix lane addresses (offsets within a stage)
    const uint32_t aAddr = sb + (wm * 64 + (lane & 15)) * STRIDE + (lane >> 4) * 16;
    const uint32_t bAddr = sb + OFF_BSM +
        (wn * 32 + ((lane >> 4) << 3) + (lane & 7)) * STRIDE + ((lane >> 3) & 1) * 16;

    uint32_t st = 0;                 // compute-stage byte offset
    uint32_t ist = 3 * STAGE_B;      // issue-stage byte offset

    for (int c = 0; c < 8; c++) {
        CP_WAIT2();                  // stage c complete (<=2 groups pending)
        __syncthreads();             // visibility + protects buffer reuse
        if (c < 5) {
            ISSUE((c + 3) * 32, ist);
            ist = (ist == 3 * STAGE_B) ? 0u : ist + STAGE_B;
        } else {
            CP_COMMIT();             // keep group counting aligned
        }

        // B fragments for both k16 halves of this chunk (4 ldsm.x4, 16 regs)
        uint32_t bf[2][2][4];
#pragma unroll
        for (int k16 = 0; k16 < 2; k16++)
#pragma unroll
            for (int np = 0; np < 2; np++)
                ldsm4(bf[k16][np], bAddr + st + np * (16 * STRIDE) + k16 * 32);

        // A fragments pipelined one (k16, mt) step ahead
        uint32_t acur[4], anxt[4];
        ldsm4(acur, aAddr + st);     // (k16=0, mt=0)
#pragma unroll
        for (int s = 0; s < 8; s++) {
            const int k16 = s >> 2, mt = s & 3;
            if (s < 7) {
                const int s2 = s + 1;
                ldsm4(anxt, aAddr + st + (s2 & 3) * (16 * STRIDE) + (s2 >> 2) * 32);
            }
#pragma unroll
            for (int np = 0; np < 2; np++) {
#pragma unroll
                for (int half = 0; half < 2; half++) {
                    mma16816(acc[mt][np * 2 + half], acur,
                             bf[k16][np][half * 2], bf[k16][np][half * 2 + 1]);
                }
            }
#pragma unroll
            for (int i = 0; i < 4; i++) acur[i] = anxt[i];
        }
        st = (st == 3 * STAGE_B) ? 0u : st + STAGE_B;
    }

    // Epilogue: hoist BN constants to registers once, then scale + store
    float inv[8], b2[8];
#pragma unroll
    for (int nt = 0; nt < 4; nt++) {
        const int cl = wn * 32 + nt * 8 + tg * 2;
        inv[nt * 2]     = sinv[cl];
        inv[nt * 2 + 1] = sinv[cl + 1];
        b2[nt * 2]      = sbb[cl];
        b2[nt * 2 + 1]  = sbb[cl + 1];
    }
#pragma unroll
    for (int mt = 0; mt < 4; mt++) {
        const int row0 = bm + wm * 64 + mt * 16 + r;
#pragma unroll
        for (int nt = 0; nt < 4; nt++) {
            const int cl = wn * 32 + nt * 8 + tg * 2;   // local col 0..127
            float2 v0, v1;
            v0.x = fmaf(acc[mt][nt][0], inv[nt * 2],     b2[nt * 2]);
            v0.y = fmaf(acc[mt][nt][1], inv[nt * 2 + 1], b2[nt * 2 + 1]);
            v1.x = fmaf(acc[mt][nt][2], inv[nt * 2],     b2[nt * 2]);
            v1.y = fmaf(acc[mt][nt][3], inv[nt * 2 + 1], b2[nt * 2 + 1]);
            *(float2*)(out + (size_t)row0 * CC + bn + cl)       = v0;
            *(float2*)(out + (size_t)(row0 + 8) * CC + bn + cl) = v1;
        }
    }
#undef ISSUE
}

// ---------------------------------------------------------------------------
// Launch
// ---------------------------------------------------------------------------
extern "C" void kernel_launch(void* const* d_in, const int* in_sizes, int n_in,
                              void* d_out, int out_size)
{
    const float* x     = (const float*)d_in[0];
    const float* dwk   = (const float*)d_in[1];
    const float* dwb   = (const float*)d_in[2];
    const float* pwk   = (const float*)d_in[3];
    const float* pwb   = (const float*)d_in[4];
    const float* gma   = (const float*)d_in[5];
    const float* bta   = (const float*)d_in[6];
    const float* mmean = (const float*)d_in[7];
    const float* mvar  = (const float*)d_in[8];
    float* out = (float*)d_out;

    static int smem_set = 0;
    if (!smem_set) {
        cudaFuncSetAttribute(fused_kernel,
                             cudaFuncAttributeMaxDynamicSharedMemorySize, SMEM_BYTES);
        smem_set = 1;
    }

    prep_kernel<<<256, 256>>>(pwk);
    fused_kernel<<<TOTAL_BLOCKS, 256, SMEM_BYTES>>>(
        x, dwk, dwb, pwb, gma, bta, mmean, mvar, out);
}